// round 10
// baseline (speedup 1.0000x reference)
#include <cuda_runtime.h>
#include <cuda_fp16.h>
#include <cstdint>

#define HH 128
#define TT 512
#define BB 220
#define NROWS 660
#define NCLUSTER 74
#define RPC 9
#define NROWS_PAD (NCLUSTER*RPC)   // 666
#define NBLOCKS (NCLUSTER*2)
#define NTHREADS 512

// h smem geometry (halfs): row stride 136 (=272B, conflict-free ldmatrix),
// plane stride 16*136=2176, buffer stride 2*2176=4352
#define HROW 136
#define HPL  (16*HROW)
#define HBUF (2*HPL)

// ex geometry (floats): [16 rows][264]; item (row,jq) gates at row*264+jq*4
#define EXROW 264

// smem byte offsets
#define SM_H    0
#define SM_EX   (2*HBUF*2)                 // 17408
#define SM_X    (SM_EX + 16*EXROW*4)       // 34304
#define SM_MBAR (SM_X + RPC*TT*2*4)        // 71168
#define SM_BYTES (SM_MBAR + 16)

__device__ float g_hout[(size_t)NROWS_PAD * TT * HH];

__device__ __forceinline__ float tanhap(float x) {
  float y;
  asm("tanh.approx.f32 %0, %1;" : "=f"(y) : "f"(x));
  return y;
}
__device__ __forceinline__ void mbar_arrive_remote_rel(unsigned raddr) {
  asm volatile("mbarrier.arrive.release.cluster.shared::cluster.b64 _, [%0];"
               :: "r"(raddr) : "memory");
}
__device__ __forceinline__ void mbar_wait_parity_acq(unsigned addr, unsigned parity) {
  asm volatile(
      "{\n\t.reg .pred P;\n\t"
      "WL_%=:\n\t"
      "mbarrier.try_wait.parity.acquire.cluster.shared::cta.b64 P, [%0], %1, 0x989680;\n\t"
      "@P bra.uni WD_%=;\n\t"
      "bra.uni WL_%=;\n\t"
      "WD_%=:\n\t}"
      :: "r"(addr), "r"(parity) : "memory");
}
__device__ __forceinline__ void ldsm4(uint32_t a[4], unsigned addr) {
  asm volatile("ldmatrix.sync.aligned.m8n8.x4.shared.b16 {%0,%1,%2,%3}, [%4];"
               : "=r"(a[0]), "=r"(a[1]), "=r"(a[2]), "=r"(a[3]) : "r"(addr));
}
__device__ __forceinline__ void mma16816(float c[4], const uint32_t a[4],
                                         const uint32_t b[2]) {
  asm volatile("mma.sync.aligned.m16n8k16.row.col.f32.f16.f16.f32 "
               "{%0,%1,%2,%3}, {%4,%5,%6,%7}, {%8,%9}, {%0,%1,%2,%3};"
               : "+f"(c[0]), "+f"(c[1]), "+f"(c[2]), "+f"(c[3])
               : "r"(a[0]), "r"(a[1]), "r"(a[2]), "r"(a[3]),
                 "r"(b[0]), "r"(b[1]));
}
__device__ __forceinline__ uint32_t packh2(float v0, float v1) {
  __half2 h = __floats2half2_rn(v0, v1);
  return *(uint32_t*)&h;
}

extern __shared__ char smem_c[];

__global__ void __cluster_dims__(2,1,1) __launch_bounds__(NTHREADS, 1)
lstm_kernel(const float* __restrict__ x0p, const float* __restrict__ x1p,
            const float* __restrict__ x2p,
            const float* __restrict__ W_ih, const float* __restrict__ W_hh,
            const float* __restrict__ b_ih, const float* __restrict__ b_hh)
{
  __half* h_sm = (__half*)(smem_c + SM_H);
  float*  ex   = (float*)(smem_c + SM_EX);
  float*  x_sm = (float*)(smem_c + SM_X);

  const int tid  = threadIdx.x;
  unsigned rank;
  asm("mov.u32 %0, %%cluster_ctarank;" : "=r"(rank));
  const int cid  = blockIdx.x >> 1;
  const int row0 = cid * RPC;

  const int w    = tid >> 5;          // warp 0..15: N-slice [w*16, w*16+16)
  const int lane = tid & 31;
  const int t4   = lane & 3;
  const int g8   = lane >> 2;

  // ---- persistent B fragments: [nt 2][seq s 8][pair 2], hi and lo planes ----
  uint32_t bhi[2][8][2], blo[2][8][2];
  {
    #pragma unroll
    for (int nt = 0; nt < 2; ++nt) {
      int n    = w*16 + nt*8 + g8;
      int gate = n & 3, jqw = n >> 2;
      int grow = gate*128 + (int)rank*64 + jqw;
      float sc = (gate == 2) ? 1.f : 0.5f;
      const float* wr = W_hh + (size_t)grow * HH;
      #pragma unroll
      for (int s = 0; s < 8; ++s) {
        int kt = ((s < 4) ? (int)rank : (int)(rank ^ 1u))*4 + (s & 3);
        #pragma unroll
        for (int pr = 0; pr < 2; ++pr) {
          int ks = kt*16 + 2*t4 + pr*8;
          float v0 = wr[ks] * sc, v1 = wr[ks+1] * sc;
          __half h0 = __float2half_rn(v0), h1 = __float2half_rn(v1);
          float  l0 = v0 - __half2float(h0), l1 = v1 - __half2float(h1);
          bhi[nt][s][pr] = packh2(__half2float(h0), __half2float(h1));
          blo[nt][s][pr] = packh2(l0, l1);
        }
      }
    }
  }

  // ---- preload x; zero h planes ----
  for (int idx = tid; idx < RPC*TT; idx += NTHREADS) {
    int r = idx >> 9, t = idx & (TT-1);
    int row = row0 + r;
    float vx = 0.f, vy = 0.f;
    if (row < NROWS) {
      const float* xp; int b;
      if (row < BB)        { xp = x0p; b = row; }
      else if (row < 2*BB) { xp = x1p; b = row - BB; }
      else                 { xp = x2p; b = row - 2*BB; }
      float4 v = *(const float4*)(xp + ((size_t)b*TT + t)*4);
      vx = v.x; vy = v.y;
    }
    x_sm[(r*TT + t)*2]     = vx;
    x_sm[(r*TT + t)*2 + 1] = vy;
  }
  for (int i = tid; i < 2*HBUF/2; i += NTHREADS)
    ((uint32_t*)h_sm)[i] = 0u;

  // ---- mbarriers: ping-pong, count 512 ----
  unsigned mbar_base = (unsigned)__cvta_generic_to_shared(smem_c + SM_MBAR);
  unsigned mbarL[2] = { mbar_base, mbar_base + 8 };
  if (tid == 0) {
    asm volatile("mbarrier.init.shared.b64 [%0], %1;" :: "r"(mbarL[0]), "r"(512u) : "memory");
    asm volatile("mbarrier.init.shared.b64 [%0], %1;" :: "r"(mbarL[1]), "r"(512u) : "memory");
  }
  unsigned mbarR[2];
  #pragma unroll
  for (int i = 0; i < 2; ++i)
    asm("mapa.shared::cluster.u32 %0, %1, %2;" : "=r"(mbarR[i])
        : "r"(mbarL[i]), "r"(rank ^ 1u));

  // ---- epilogue constants (warp-local jq range [4w, 4w+4)) ----
  const int e_jq = 4*w + t4;             // this thread's j-quarter index
  const int e_r1 = g8;                   // item1 row 0..7
  const bool has2 = (lane < 4);          // item2: row 8, jq = 4w+lane
  const int e_jg = (int)rank*64 + e_jq;
  float biasr[4], wi0[4], wi1[4];
  #pragma unroll
  for (int g = 0; g < 4; ++g) {
    const float sc = (g == 2) ? 1.f : 0.5f;
    int grow = g*128 + e_jg;
    biasr[g] = (b_ih[grow] + b_hh[grow]) * sc;
    wi0[g]   = W_ih[grow*2] * sc;
    wi1[g]   = W_ih[grow*2 + 1] * sc;
  }
  float c_state[2] = {0.f, 0.f};

  const unsigned h_base = (unsigned)__cvta_generic_to_shared(h_sm);
  const unsigned a_lane_off = (unsigned)((lane & 15)*(HROW*2) + (lane >> 4)*16);

  __syncthreads();
  asm volatile("barrier.cluster.arrive.aligned;" ::: "memory");
  asm volatile("barrier.cluster.wait.aligned;"   ::: "memory");

  const int rank4a = (int)rank*4, rank4b = (int)(rank ^ 1u)*4;

  for (int t = 0; t < TT; ++t) {
    const int buf = t & 1, nxt = buf ^ 1;

    float cacc[2][4];
    #pragma unroll
    for (int nt = 0; nt < 2; ++nt)
      #pragma unroll
      for (int i = 0; i < 4; ++i) cacc[nt][i] = 0.f;

    const unsigned hb = h_base + (unsigned)buf*(HBUF*2) + a_lane_off;

    #pragma unroll
    for (int s = 0; s < 8; ++s) {
      if (s == 4 && t > 0)
        mbar_wait_parity_acq(mbarL[(t-1) & 1], (unsigned)(((t-1) >> 1) & 1));
      int kt = ((s < 4) ? rank4a : rank4b) + (s & 3);
      unsigned aaddr = hb + (unsigned)kt*32;
      uint32_t ahi[4], alo[4];
      ldsm4(ahi, aaddr);
      ldsm4(alo, aaddr + HPL*2);
      #pragma unroll
      for (int nt = 0; nt < 2; ++nt) {
        mma16816(cacc[nt], ahi, bhi[nt][s]);
        mma16816(cacc[nt], ahi, blo[nt][s]);
        mma16816(cacc[nt], alo, bhi[nt][s]);
      }
    }

    // ---- publish gates to warp-local ex region: [row][jq*4 + gate] ----
    #pragma unroll
    for (int nt = 0; nt < 2; ++nt) {
      int jqw = w*4 + nt*2 + (t4 >> 1);
      int gb  = (t4 & 1)*2;
      float* p = ex + g8*EXROW + jqw*4 + gb;
      *(float2*)p               = make_float2(cacc[nt][0], cacc[nt][1]);
      *(float2*)(p + 8*EXROW)   = make_float2(cacc[nt][2], cacc[nt][3]);
    }
    __syncwarp();

    // ---- epilogue: warp-local items (row, jq in [4w,4w+4)) ----
    {
      float hval[2];
      #pragma unroll
      for (int it = 0; it < 2; ++it) {
        if (it == 1 && !has2) break;
        int rr = (it == 0) ? e_r1 : 8;
        float2 xv = *(const float2*)(x_sm + (rr*TT + t)*2);
        float4 g4 = *(const float4*)(ex + rr*EXROW + e_jq*4);
        float gi = g4.x + biasr[0] + wi0[0]*xv.x + wi1[0]*xv.y;
        float gf = g4.y + biasr[1] + wi0[1]*xv.x + wi1[1]*xv.y;
        float gg = g4.z + biasr[2] + wi0[2]*xv.x + wi1[2]*xv.y;
        float go = g4.w + biasr[3] + wi0[3]*xv.x + wi1[3]*xv.y;
        float ig = 0.5f*tanhap(gi) + 0.5f;
        float fg = 0.5f*tanhap(gf) + 0.5f;
        float gt = tanhap(gg);
        float og = 0.5f*tanhap(go) + 0.5f;
        float c  = fg * c_state[it] + ig * gt;
        c_state[it] = c;
        float h  = og * tanhap(c);
        hval[it] = h;

        __half hh = __float2half_rn(h);
        __half hl = __float2half_rn(h - __half2float(hh));
        int idx_hi = nxt*HBUF + rr*HROW + e_jg;
        int idx_lo = idx_hi + HPL;
        h_sm[idx_hi] = hh;
        h_sm[idx_lo] = hl;
        unsigned lhi = (unsigned)__cvta_generic_to_shared(h_sm + idx_hi);
        unsigned llo = (unsigned)__cvta_generic_to_shared(h_sm + idx_lo);
        unsigned rhi, rlo;
        asm("mapa.shared::cluster.u32 %0, %1, %2;" : "=r"(rhi) : "r"(lhi), "r"(rank ^ 1u));
        asm("mapa.shared::cluster.u32 %0, %1, %2;" : "=r"(rlo) : "r"(llo), "r"(rank ^ 1u));
        asm volatile("st.shared::cluster.b16 [%0], %1;"
                     :: "r"(rhi), "h"((unsigned short)__half_as_ushort(hh)) : "memory");
        asm volatile("st.shared::cluster.b16 [%0], %1;"
                     :: "r"(rlo), "h"((unsigned short)__half_as_ushort(hl)) : "memory");
      }
      mbar_arrive_remote_rel(mbarR[buf]);

      g_hout[((size_t)(row0 + e_r1)*TT + t)*HH + e_jg] = hval[0];
      if (has2)
        g_hout[((size_t)(row0 + 8)*TT + t)*HH + e_jg] = hval[1];
    }
    __syncthreads();   // all local h(t) visible before any warp's mma(t+1)
  }

  asm volatile("barrier.cluster.arrive.aligned;" ::: "memory");
  asm volatile("barrier.cluster.wait.aligned;"   ::: "memory");
}

// ---------------- distance / gather kernel ----------------
__global__ void dist_kernel(const int* __restrict__ Lt, const int* __restrict__ La,
                            const int* __restrict__ Lf,
                            const int* __restrict__ tasl, const int* __restrict__ tfsl,
                            const int* __restrict__ asl,  const int* __restrict__ fsl,
                            float* __restrict__ out)
{
  int g = (blockIdx.x * blockDim.x + threadIdx.x) >> 5;
  int lane = threadIdx.x & 31;
  if (g >= 4840) return;
  int rowA, tA, rowB, tB;
  if (g < 220)       { int b = g;       rowA = b;  tA = max(Lt[b]-1, 0);   rowB = 220+b; tB = max(La[b]-1, 0); }
  else if (g < 440)  { int b = g-220;   rowA = b;  tA = max(Lt[b]-1, 0);   rowB = 440+b; tB = max(Lf[b]-1, 0); }
  else if (g < 2640) { int k = g-440;   int b = k/10; rowA = b; tA = max(tasl[k]-1, 0); rowB = 220+b; tB = max(asl[k]-1, 0); }
  else               { int k = g-2640;  int b = k/10; rowA = b; tA = max(tfsl[k]-1, 0); rowB = 440+b; tB = max(fsl[k]-1, 0); }

  const float4* pa = (const float4*)(g_hout + ((size_t)rowA*TT + tA)*HH);
  const float4* pb = (const float4*)(g_hout + ((size_t)rowB*TT + tB)*HH);
  float4 a = pa[lane], b4 = pb[lane];
  float dx = a.x-b4.x, dy = a.y-b4.y, dz = a.z-b4.z, dw = a.w-b4.w;
  float s = dx*dx + dy*dy + dz*dz + dw*dw;
  #pragma unroll
  for (int off = 16; off; off >>= 1) s += __shfl_xor_sync(0xffffffffu, s, off);
  if (lane == 0) out[g] = __expf(-__fsqrt_rn(s));
}

extern "C" void kernel_launch(void* const* d_in, const int* in_sizes, int n_in,
                              void* d_out, int out_size)
{
  const float* traj = (const float*)d_in[0];
  const int*   Lt   = (const int*)  d_in[1];
  const int*   tasl = (const int*)  d_in[2];
  const int*   tfsl = (const int*)  d_in[3];
  const float* anch = (const float*)d_in[4];
  const int*   La   = (const int*)  d_in[5];
  const int*   asl  = (const int*)  d_in[6];
  const float* fare = (const float*)d_in[7];
  const int*   Lf   = (const int*)  d_in[8];
  const int*   fsl  = (const int*)  d_in[9];
  const float* W_ih = (const float*)d_in[10];
  const float* W_hh = (const float*)d_in[11];
  const float* b_ih = (const float*)d_in[12];
  const float* b_hh = (const float*)d_in[13];

  cudaFuncSetAttribute(lstm_kernel, cudaFuncAttributeMaxDynamicSharedMemorySize,
                       SM_BYTES);
  lstm_kernel<<<NBLOCKS, NTHREADS, SM_BYTES>>>(traj, anch, fare, W_ih, W_hh,
                                               b_ih, b_hh);
  dist_kernel<<<(4840*32 + 255)/256, 256>>>(Lt, La, Lf, tasl, tfsl, asl, fsl,
                                            (float*)d_out);
}

// round 11
// speedup vs baseline: 1.3350x; 1.3350x over previous
#include <cuda_runtime.h>
#include <cuda_fp16.h>
#include <cstdint>

#define HH 128
#define TT 512
#define BB 220
#define NROWS 660
#define NCLUSTER 74
#define RPC 9
#define NROWS_PAD (NCLUSTER*RPC)   // 666
#define NBLOCKS (NCLUSTER*2)
#define NTHREADS 512

// h smem geometry (halfs): row stride 136 (=272B, conflict-free ldmatrix),
// one hi-plane per buffer: HBUF = 16*136 halfs; two buffers
#define HROW 136
#define HBUF (16*HROW)

// ex geometry (floats): [16 rows][264]; item (row,jq) gates at row*264+jq*4
#define EXROW 264

// smem byte offsets
#define SM_H    0
#define SM_EX   (2*HBUF*2)                 // 8704
#define SM_X    (SM_EX + 16*EXROW*4)       // 8704+16896 = 25600
#define SM_MBAR (SM_X + RPC*TT*2*4)        // +36864 = 62464
#define SM_BYTES (SM_MBAR + 16)

__device__ float g_hout[(size_t)NROWS_PAD * TT * HH];

__device__ __forceinline__ float tanhap(float x) {
  float y;
  asm("tanh.approx.f32 %0, %1;" : "=f"(y) : "f"(x));
  return y;
}
__device__ __forceinline__ void mbar_arrive_remote_rel(unsigned raddr) {
  asm volatile("mbarrier.arrive.release.cluster.shared::cluster.b64 _, [%0];"
               :: "r"(raddr) : "memory");
}
__device__ __forceinline__ void mbar_wait_parity_acq(unsigned addr, unsigned parity) {
  asm volatile(
      "{\n\t.reg .pred P;\n\t"
      "WL_%=:\n\t"
      "mbarrier.try_wait.parity.acquire.cluster.shared::cta.b64 P, [%0], %1, 0x989680;\n\t"
      "@P bra.uni WD_%=;\n\t"
      "bra.uni WL_%=;\n\t"
      "WD_%=:\n\t}"
      :: "r"(addr), "r"(parity) : "memory");
}
__device__ __forceinline__ void ldsm4(uint32_t a[4], unsigned addr) {
  asm volatile("ldmatrix.sync.aligned.m8n8.x4.shared.b16 {%0,%1,%2,%3}, [%4];"
               : "=r"(a[0]), "=r"(a[1]), "=r"(a[2]), "=r"(a[3]) : "r"(addr));
}
__device__ __forceinline__ void mma16816(float c[4], const uint32_t a[4],
                                         const uint32_t b[2]) {
  asm volatile("mma.sync.aligned.m16n8k16.row.col.f32.f16.f16.f32 "
               "{%0,%1,%2,%3}, {%4,%5,%6,%7}, {%8,%9}, {%0,%1,%2,%3};"
               : "+f"(c[0]), "+f"(c[1]), "+f"(c[2]), "+f"(c[3])
               : "r"(a[0]), "r"(a[1]), "r"(a[2]), "r"(a[3]),
                 "r"(b[0]), "r"(b[1]));
}
__device__ __forceinline__ uint32_t packh2(float v0, float v1) {
  __half2 h = __floats2half2_rn(v0, v1);
  return *(uint32_t*)&h;
}

extern __shared__ char smem_c[];

__global__ void __cluster_dims__(2,1,1) __launch_bounds__(NTHREADS, 1)
lstm_kernel(const float* __restrict__ x0p, const float* __restrict__ x1p,
            const float* __restrict__ x2p,
            const float* __restrict__ W_ih, const float* __restrict__ W_hh,
            const float* __restrict__ b_ih, const float* __restrict__ b_hh)
{
  __half* h_sm = (__half*)(smem_c + SM_H);
  float*  ex   = (float*)(smem_c + SM_EX);
  float*  x_sm = (float*)(smem_c + SM_X);

  const int tid  = threadIdx.x;
  unsigned rank;
  asm("mov.u32 %0, %%cluster_ctarank;" : "=r"(rank));
  const int cid  = blockIdx.x >> 1;
  const int row0 = cid * RPC;

  const int w    = tid >> 5;          // warp 0..15: N-slice [w*16, w*16+16)
  const int lane = tid & 31;
  const int t4   = lane & 3;
  const int g8   = lane >> 2;

  // ---- persistent B fragments: W_hi and W_lo planes, [nt 2][s 8][pair 2] ----
  uint32_t bhi[2][8][2], blo[2][8][2];
  {
    #pragma unroll
    for (int nt = 0; nt < 2; ++nt) {
      int n    = w*16 + nt*8 + g8;
      int gate = n & 3, jqw = n >> 2;
      int grow = gate*128 + (int)rank*64 + jqw;
      float sc = (gate == 2) ? 1.f : 0.5f;
      const float* wr = W_hh + (size_t)grow * HH;
      #pragma unroll
      for (int s = 0; s < 8; ++s) {
        int kt = ((s < 4) ? (int)rank : (int)(rank ^ 1u))*4 + (s & 3);
        #pragma unroll
        for (int pr = 0; pr < 2; ++pr) {
          int ks = kt*16 + 2*t4 + pr*8;
          float v0 = wr[ks] * sc, v1 = wr[ks+1] * sc;
          __half h0 = __float2half_rn(v0), h1 = __float2half_rn(v1);
          float  l0 = v0 - __half2float(h0), l1 = v1 - __half2float(h1);
          bhi[nt][s][pr] = packh2(__half2float(h0), __half2float(h1));
          blo[nt][s][pr] = packh2(l0, l1);
        }
      }
    }
  }

  // ---- preload x; zero h planes ----
  for (int idx = tid; idx < RPC*TT; idx += NTHREADS) {
    int r = idx >> 9, t = idx & (TT-1);
    int row = row0 + r;
    float vx = 0.f, vy = 0.f;
    if (row < NROWS) {
      const float* xp; int b;
      if (row < BB)        { xp = x0p; b = row; }
      else if (row < 2*BB) { xp = x1p; b = row - BB; }
      else                 { xp = x2p; b = row - 2*BB; }
      float4 v = *(const float4*)(xp + ((size_t)b*TT + t)*4);
      vx = v.x; vy = v.y;
    }
    x_sm[(r*TT + t)*2]     = vx;
    x_sm[(r*TT + t)*2 + 1] = vy;
  }
  for (int i = tid; i < 2*HBUF/2; i += NTHREADS)
    ((uint32_t*)h_sm)[i] = 0u;

  // ---- mbarriers: ping-pong, count 512 ----
  unsigned mbar_base = (unsigned)__cvta_generic_to_shared(smem_c + SM_MBAR);
  unsigned mbarL[2] = { mbar_base, mbar_base + 8 };
  if (tid == 0) {
    asm volatile("mbarrier.init.shared.b64 [%0], %1;" :: "r"(mbarL[0]), "r"(512u) : "memory");
    asm volatile("mbarrier.init.shared.b64 [%0], %1;" :: "r"(mbarL[1]), "r"(512u) : "memory");
  }
  unsigned mbarR[2];
  #pragma unroll
  for (int i = 0; i < 2; ++i)
    asm("mapa.shared::cluster.u32 %0, %1, %2;" : "=r"(mbarR[i])
        : "r"(mbarL[i]), "r"(rank ^ 1u));

  // ---- epilogue constants (warp-local jq range [4w, 4w+4)) ----
  const int e_jq = 4*w + t4;
  const int e_r1 = g8;                   // item1 row 0..7
  const bool has2 = (lane < 4);          // item2: row 8
  const int e_jg = (int)rank*64 + e_jq;
  float biasr[4], wi0[4], wi1[4];
  #pragma unroll
  for (int g = 0; g < 4; ++g) {
    const float sc = (g == 2) ? 1.f : 0.5f;
    int grow = g*128 + e_jg;
    biasr[g] = (b_ih[grow] + b_hh[grow]) * sc;
    wi0[g]   = W_ih[grow*2] * sc;
    wi1[g]   = W_ih[grow*2 + 1] * sc;
  }
  float c_state[2] = {0.f, 0.f};

  const unsigned h_base = (unsigned)__cvta_generic_to_shared(h_sm);
  const unsigned a_lane_off = (unsigned)((lane & 15)*(HROW*2) + (lane >> 4)*16);

  __syncthreads();
  asm volatile("barrier.cluster.arrive.aligned;" ::: "memory");
  asm volatile("barrier.cluster.wait.aligned;"   ::: "memory");

  const int rank4a = (int)rank*4, rank4b = (int)(rank ^ 1u)*4;

  for (int t = 0; t < TT; ++t) {
    const int buf = t & 1, nxt = buf ^ 1;

    // per-term accumulators: [nt][term] -> 4 independent mma chains of 8
    float accA[2][4], accB[2][4];
    #pragma unroll
    for (int nt = 0; nt < 2; ++nt)
      #pragma unroll
      for (int i = 0; i < 4; ++i) { accA[nt][i] = 0.f; accB[nt][i] = 0.f; }

    const unsigned hb = h_base + (unsigned)buf*(HBUF*2) + a_lane_off;

    #pragma unroll
    for (int s = 0; s < 8; ++s) {
      if (s == 4 && t > 0)
        mbar_wait_parity_acq(mbarL[(t-1) & 1], (unsigned)(((t-1) >> 1) & 1));
      int kt = ((s < 4) ? rank4a : rank4b) + (s & 3);
      uint32_t ahi[4];
      ldsm4(ahi, hb + (unsigned)kt*32);
      #pragma unroll
      for (int nt = 0; nt < 2; ++nt) {
        mma16816(accA[nt], ahi, bhi[nt][s]);
        mma16816(accB[nt], ahi, blo[nt][s]);
      }
    }

    // ---- publish gates to warp-local ex region: [row][jq*4 + gate] ----
    #pragma unroll
    for (int nt = 0; nt < 2; ++nt) {
      int jqw = w*4 + nt*2 + (t4 >> 1);
      int gb  = (t4 & 1)*2;
      float* p = ex + g8*EXROW + jqw*4 + gb;
      *(float2*)p             = make_float2(accA[nt][0] + accB[nt][0],
                                            accA[nt][1] + accB[nt][1]);
      *(float2*)(p + 8*EXROW) = make_float2(accA[nt][2] + accB[nt][2],
                                            accA[nt][3] + accB[nt][3]);
    }
    __syncwarp();

    // ---- epilogue: warp-local items (row, jq in [4w,4w+4)) ----
    {
      float hval[2];
      #pragma unroll
      for (int it = 0; it < 2; ++it) {
        if (it == 1 && !has2) break;
        int rr = (it == 0) ? e_r1 : 8;
        float2 xv = *(const float2*)(x_sm + (rr*TT + t)*2);
        float4 g4 = *(const float4*)(ex + rr*EXROW + e_jq*4);
        float gi = g4.x + biasr[0] + wi0[0]*xv.x + wi1[0]*xv.y;
        float gf = g4.y + biasr[1] + wi0[1]*xv.x + wi1[1]*xv.y;
        float gg = g4.z + biasr[2] + wi0[2]*xv.x + wi1[2]*xv.y;
        float go = g4.w + biasr[3] + wi0[3]*xv.x + wi1[3]*xv.y;
        float ig = 0.5f*tanhap(gi) + 0.5f;
        float fg = 0.5f*tanhap(gf) + 0.5f;
        float gt = tanhap(gg);
        float og = 0.5f*tanhap(go) + 0.5f;
        float c  = fg * c_state[it] + ig * gt;
        c_state[it] = c;
        float h  = og * tanhap(c);
        hval[it] = h;

        __half hh = __float2half_rn(h);
        int idx_hi = nxt*HBUF + rr*HROW + e_jg;
        h_sm[idx_hi] = hh;
        unsigned lhi = (unsigned)__cvta_generic_to_shared(h_sm + idx_hi);
        unsigned rhi;
        asm("mapa.shared::cluster.u32 %0, %1, %2;" : "=r"(rhi) : "r"(lhi), "r"(rank ^ 1u));
        asm volatile("st.shared::cluster.b16 [%0], %1;"
                     :: "r"(rhi), "h"((unsigned short)__half_as_ushort(hh)) : "memory");
      }
      mbar_arrive_remote_rel(mbarR[buf]);

      g_hout[((size_t)(row0 + e_r1)*TT + t)*HH + e_jg] = hval[0];
      if (has2)
        g_hout[((size_t)(row0 + 8)*TT + t)*HH + e_jg] = hval[1];
    }
    __syncthreads();   // all local h(t) visible before any warp's mma(t+1)
  }

  asm volatile("barrier.cluster.arrive.aligned;" ::: "memory");
  asm volatile("barrier.cluster.wait.aligned;"   ::: "memory");
}

// ---------------- distance / gather kernel ----------------
__global__ void dist_kernel(const int* __restrict__ Lt, const int* __restrict__ La,
                            const int* __restrict__ Lf,
                            const int* __restrict__ tasl, const int* __restrict__ tfsl,
                            const int* __restrict__ asl,  const int* __restrict__ fsl,
                            float* __restrict__ out)
{
  int g = (blockIdx.x * blockDim.x + threadIdx.x) >> 5;
  int lane = threadIdx.x & 31;
  if (g >= 4840) return;
  int rowA, tA, rowB, tB;
  if (g < 220)       { int b = g;       rowA = b;  tA = max(Lt[b]-1, 0);   rowB = 220+b; tB = max(La[b]-1, 0); }
  else if (g < 440)  { int b = g-220;   rowA = b;  tA = max(Lt[b]-1, 0);   rowB = 440+b; tB = max(Lf[b]-1, 0); }
  else if (g < 2640) { int k = g-440;   int b = k/10; rowA = b; tA = max(tasl[k]-1, 0); rowB = 220+b; tB = max(asl[k]-1, 0); }
  else               { int k = g-2640;  int b = k/10; rowA = b; tA = max(tfsl[k]-1, 0); rowB = 440+b; tB = max(fsl[k]-1, 0); }

  const float4* pa = (const float4*)(g_hout + ((size_t)rowA*TT + tA)*HH);
  const float4* pb = (const float4*)(g_hout + ((size_t)rowB*TT + tB)*HH);
  float4 a = pa[lane], b4 = pb[lane];
  float dx = a.x-b4.x, dy = a.y-b4.y, dz = a.z-b4.z, dw = a.w-b4.w;
  float s = dx*dx + dy*dy + dz*dz + dw*dw;
  #pragma unroll
  for (int off = 16; off; off >>= 1) s += __shfl_xor_sync(0xffffffffu, s, off);
  if (lane == 0) out[g] = __expf(-__fsqrt_rn(s));
}

extern "C" void kernel_launch(void* const* d_in, const int* in_sizes, int n_in,
                              void* d_out, int out_size)
{
  const float* traj = (const float*)d_in[0];
  const int*   Lt   = (const int*)  d_in[1];
  const int*   tasl = (const int*)  d_in[2];
  const int*   tfsl = (const int*)  d_in[3];
  const float* anch = (const float*)d_in[4];
  const int*   La   = (const int*)  d_in[5];
  const int*   asl  = (const int*)  d_in[6];
  const float* fare = (const float*)d_in[7];
  const int*   Lf   = (const int*)  d_in[8];
  const int*   fsl  = (const int*)  d_in[9];
  const float* W_ih = (const float*)d_in[10];
  const float* W_hh = (const float*)d_in[11];
  const float* b_ih = (const float*)d_in[12];
  const float* b_hh = (const float*)d_in[13];

  cudaFuncSetAttribute(lstm_kernel, cudaFuncAttributeMaxDynamicSharedMemorySize,
                       SM_BYTES);
  lstm_kernel<<<NBLOCKS, NTHREADS, SM_BYTES>>>(traj, anch, fare, W_ih, W_hh,
                                               b_ih, b_hh);
  dist_kernel<<<(4840*32 + 255)/256, 256>>>(Lt, La, Lf, tasl, tfsl, asl, fsl,
                                            (float*)d_out);
}

// round 12
// speedup vs baseline: 1.4702x; 1.1012x over previous
#include <cuda_runtime.h>
#include <cuda_fp16.h>
#include <cstdint>

#define HH 128
#define TT 512
#define BB 220
#define NROWS 660
#define NCLUSTER 74
#define RPC 9
#define NROWS_PAD (NCLUSTER*RPC)   // 666
#define NBLOCKS (NCLUSTER*2)
#define NTHREADS 512

// h smem geometry (halfs): row stride 136 (=272B, conflict-free ldmatrix),
// one plane per buffer: HBUF = 16*136 halfs; two buffers
#define HROW 136
#define HBUF (16*HROW)

// ex geometry (floats): [16 rows][264]; item (row,jq) gates at row*264+jq*4
#define EXROW 264

// smem byte offsets
#define SM_H    0
#define SM_EX   (2*HBUF*2)                 // 8704
#define SM_X    (SM_EX + 16*EXROW*4)       // 25600
#define SM_MBAR (SM_X + RPC*TT*2*4)        // 62464
#define SM_BYTES (SM_MBAR + 16)

__device__ float g_hout[(size_t)NROWS_PAD * TT * HH];

__device__ __forceinline__ float tanhap(float x) {
  float y;
  asm("tanh.approx.f32 %0, %1;" : "=f"(y) : "f"(x));
  return y;
}
__device__ __forceinline__ void mbar_arrive_remote_rel(unsigned raddr) {
  asm volatile("mbarrier.arrive.release.cluster.shared::cluster.b64 _, [%0];"
               :: "r"(raddr) : "memory");
}
__device__ __forceinline__ void mbar_wait_parity_acq(unsigned addr, unsigned parity) {
  asm volatile(
      "{\n\t.reg .pred P;\n\t"
      "WL_%=:\n\t"
      "mbarrier.try_wait.parity.acquire.cluster.shared::cta.b64 P, [%0], %1, 0x989680;\n\t"
      "@P bra.uni WD_%=;\n\t"
      "bra.uni WL_%=;\n\t"
      "WD_%=:\n\t}"
      :: "r"(addr), "r"(parity) : "memory");
}
__device__ __forceinline__ void ldsm4(uint32_t a[4], unsigned addr) {
  asm volatile("ldmatrix.sync.aligned.m8n8.x4.shared.b16 {%0,%1,%2,%3}, [%4];"
               : "=r"(a[0]), "=r"(a[1]), "=r"(a[2]), "=r"(a[3]) : "r"(addr));
}
__device__ __forceinline__ void mma16816(float c[4], const uint32_t a[4],
                                         const uint32_t b[2]) {
  asm volatile("mma.sync.aligned.m16n8k16.row.col.f32.f16.f16.f32 "
               "{%0,%1,%2,%3}, {%4,%5,%6,%7}, {%8,%9}, {%0,%1,%2,%3};"
               : "+f"(c[0]), "+f"(c[1]), "+f"(c[2]), "+f"(c[3])
               : "r"(a[0]), "r"(a[1]), "r"(a[2]), "r"(a[3]),
                 "r"(b[0]), "r"(b[1]));
}
__device__ __forceinline__ uint32_t packh2(float v0, float v1) {
  __half2 h = __floats2half2_rn(v0, v1);
  return *(uint32_t*)&h;
}

extern __shared__ char smem_c[];

__global__ void __cluster_dims__(2,1,1) __launch_bounds__(NTHREADS, 1)
lstm_kernel(const float* __restrict__ x0p, const float* __restrict__ x1p,
            const float* __restrict__ x2p,
            const float* __restrict__ W_ih, const float* __restrict__ W_hh,
            const float* __restrict__ b_ih, const float* __restrict__ b_hh)
{
  __half* h_sm = (__half*)(smem_c + SM_H);
  float*  ex   = (float*)(smem_c + SM_EX);
  float*  x_sm = (float*)(smem_c + SM_X);

  const int tid  = threadIdx.x;
  unsigned rank;
  asm("mov.u32 %0, %%cluster_ctarank;" : "=r"(rank));
  const int cid  = blockIdx.x >> 1;
  const int row0 = cid * RPC;

  const int w    = tid >> 5;          // warp 0..15: N-slice [w*16, w*16+16)
  const int lane = tid & 31;
  const int t4   = lane & 3;
  const int g8   = lane >> 2;

  // ---- persistent B fragments: fp16-rounded W, [nt 2][s 8][pair 2] ----
  uint32_t bfr[2][8][2];
  {
    #pragma unroll
    for (int nt = 0; nt < 2; ++nt) {
      int n    = w*16 + nt*8 + g8;
      int gate = n & 3, jqw = n >> 2;
      int grow = gate*128 + (int)rank*64 + jqw;
      float sc = (gate == 2) ? 1.f : 0.5f;
      const float* wr = W_hh + (size_t)grow * HH;
      #pragma unroll
      for (int s = 0; s < 8; ++s) {
        int kt = ((s < 4) ? (int)rank : (int)(rank ^ 1u))*4 + (s & 3);
        #pragma unroll
        for (int pr = 0; pr < 2; ++pr) {
          int ks = kt*16 + 2*t4 + pr*8;
          bfr[nt][s][pr] = packh2(wr[ks] * sc, wr[ks+1] * sc);
        }
      }
    }
  }

  // ---- preload x; zero h planes ----
  for (int idx = tid; idx < RPC*TT; idx += NTHREADS) {
    int r = idx >> 9, t = idx & (TT-1);
    int row = row0 + r;
    float vx = 0.f, vy = 0.f;
    if (row < NROWS) {
      const float* xp; int b;
      if (row < BB)        { xp = x0p; b = row; }
      else if (row < 2*BB) { xp = x1p; b = row - BB; }
      else                 { xp = x2p; b = row - 2*BB; }
      float4 v = *(const float4*)(xp + ((size_t)b*TT + t)*4);
      vx = v.x; vy = v.y;
    }
    x_sm[(r*TT + t)*2]     = vx;
    x_sm[(r*TT + t)*2 + 1] = vy;
  }
  for (int i = tid; i < 2*HBUF/2; i += NTHREADS)
    ((uint32_t*)h_sm)[i] = 0u;

  // ---- mbarriers: ping-pong, count 512 ----
  unsigned mbar_base = (unsigned)__cvta_generic_to_shared(smem_c + SM_MBAR);
  unsigned mbarL[2] = { mbar_base, mbar_base + 8 };
  if (tid == 0) {
    asm volatile("mbarrier.init.shared.b64 [%0], %1;" :: "r"(mbarL[0]), "r"(512u) : "memory");
    asm volatile("mbarrier.init.shared.b64 [%0], %1;" :: "r"(mbarL[1]), "r"(512u) : "memory");
  }
  unsigned mbarR[2];
  #pragma unroll
  for (int i = 0; i < 2; ++i)
    asm("mapa.shared::cluster.u32 %0, %1, %2;" : "=r"(mbarR[i])
        : "r"(mbarL[i]), "r"(rank ^ 1u));

  // ---- epilogue constants (warp-local jq range [4w, 4w+4)) ----
  const int e_jq = 4*w + t4;
  const int e_r1 = g8;                   // item1 row 0..7
  const bool has2 = (lane < 4);          // item2: row 8
  const int e_jg = (int)rank*64 + e_jq;
  float biasr[4], wi0[4], wi1[4];
  #pragma unroll
  for (int g = 0; g < 4; ++g) {
    const float sc = (g == 2) ? 1.f : 0.5f;
    int grow = g*128 + e_jg;
    biasr[g] = (b_ih[grow] + b_hh[grow]) * sc;
    wi0[g]   = W_ih[grow*2] * sc;
    wi1[g]   = W_ih[grow*2 + 1] * sc;
  }
  float c_state[2] = {0.f, 0.f};

  const unsigned h_base = (unsigned)__cvta_generic_to_shared(h_sm);
  const unsigned a_lane_off = (unsigned)((lane & 15)*(HROW*2) + (lane >> 4)*16);

  __syncthreads();
  asm volatile("barrier.cluster.arrive.aligned;" ::: "memory");
  asm volatile("barrier.cluster.wait.aligned;"   ::: "memory");

  const int rank4a = (int)rank*4, rank4b = (int)(rank ^ 1u)*4;

  for (int t = 0; t < TT; ++t) {
    const int buf = t & 1, nxt = buf ^ 1;

    float acc[2][4];
    #pragma unroll
    for (int nt = 0; nt < 2; ++nt)
      #pragma unroll
      for (int i = 0; i < 4; ++i) acc[nt][i] = 0.f;

    const unsigned hb = h_base + (unsigned)buf*(HBUF*2) + a_lane_off;

    #pragma unroll
    for (int s = 0; s < 8; ++s) {
      if (s == 4 && t > 0)
        mbar_wait_parity_acq(mbarL[(t-1) & 1], (unsigned)(((t-1) >> 1) & 1));
      int kt = ((s < 4) ? rank4a : rank4b) + (s & 3);
      uint32_t ahi[4];
      ldsm4(ahi, hb + (unsigned)kt*32);
      #pragma unroll
      for (int nt = 0; nt < 2; ++nt)
        mma16816(acc[nt], ahi, bfr[nt][s]);
    }

    // ---- publish gates to warp-local ex region: [row][jq*4 + gate] ----
    #pragma unroll
    for (int nt = 0; nt < 2; ++nt) {
      int jqw = w*4 + nt*2 + (t4 >> 1);
      int gb  = (t4 & 1)*2;
      float* p = ex + g8*EXROW + jqw*4 + gb;
      *(float2*)p             = make_float2(acc[nt][0], acc[nt][1]);
      *(float2*)(p + 8*EXROW) = make_float2(acc[nt][2], acc[nt][3]);
    }
    __syncwarp();

    // ---- epilogue: warp-local items (row, jq in [4w,4w+4)) ----
    {
      float hval[2];
      #pragma unroll
      for (int it = 0; it < 2; ++it) {
        if (it == 1 && !has2) break;
        int rr = (it == 0) ? e_r1 : 8;
        float2 xv = *(const float2*)(x_sm + (rr*TT + t)*2);
        float4 g4 = *(const float4*)(ex + rr*EXROW + e_jq*4);
        float gi = g4.x + biasr[0] + wi0[0]*xv.x + wi1[0]*xv.y;
        float gf = g4.y + biasr[1] + wi0[1]*xv.x + wi1[1]*xv.y;
        float gg = g4.z + biasr[2] + wi0[2]*xv.x + wi1[2]*xv.y;
        float go = g4.w + biasr[3] + wi0[3]*xv.x + wi1[3]*xv.y;
        float ig = 0.5f*tanhap(gi) + 0.5f;
        float fg = 0.5f*tanhap(gf) + 0.5f;
        float gt = tanhap(gg);
        float og = 0.5f*tanhap(go) + 0.5f;
        float c  = fg * c_state[it] + ig * gt;
        c_state[it] = c;
        float h  = og * tanhap(c);
        hval[it] = h;

        __half hh = __float2half_rn(h);
        int idx_hi = nxt*HBUF + rr*HROW + e_jg;
        h_sm[idx_hi] = hh;
        unsigned lhi = (unsigned)__cvta_generic_to_shared(h_sm + idx_hi);
        unsigned rhi;
        asm("mapa.shared::cluster.u32 %0, %1, %2;" : "=r"(rhi) : "r"(lhi), "r"(rank ^ 1u));
        asm volatile("st.shared::cluster.b16 [%0], %1;"
                     :: "r"(rhi), "h"((unsigned short)__half_as_ushort(hh)) : "memory");
      }
      mbar_arrive_remote_rel(mbarR[buf]);

      g_hout[((size_t)(row0 + e_r1)*TT + t)*HH + e_jg] = hval[0];
      if (has2)
        g_hout[((size_t)(row0 + 8)*TT + t)*HH + e_jg] = hval[1];
    }
    __syncthreads();   // all local h(t) visible before any warp's mma(t+1)
  }

  asm volatile("barrier.cluster.arrive.aligned;" ::: "memory");
  asm volatile("barrier.cluster.wait.aligned;"   ::: "memory");
}

// ---------------- distance / gather kernel ----------------
__global__ void dist_kernel(const int* __restrict__ Lt, const int* __restrict__ La,
                            const int* __restrict__ Lf,
                            const int* __restrict__ tasl, const int* __restrict__ tfsl,
                            const int* __restrict__ asl,  const int* __restrict__ fsl,
                            float* __restrict__ out)
{
  int g = (blockIdx.x * blockDim.x + threadIdx.x) >> 5;
  int lane = threadIdx.x & 31;
  if (g >= 4840) return;
  int rowA, tA, rowB, tB;
  if (g < 220)       { int b = g;       rowA = b;  tA = max(Lt[b]-1, 0);   rowB = 220+b; tB = max(La[b]-1, 0); }
  else if (g < 440)  { int b = g-220;   rowA = b;  tA = max(Lt[b]-1, 0);   rowB = 440+b; tB = max(Lf[b]-1, 0); }
  else if (g < 2640) { int k = g-440;   int b = k/10; rowA = b; tA = max(tasl[k]-1, 0); rowB = 220+b; tB = max(asl[k]-1, 0); }
  else               { int k = g-2640;  int b = k/10; rowA = b; tA = max(tfsl[k]-1, 0); rowB = 440+b; tB = max(fsl[k]-1, 0); }

  const float4* pa = (const float4*)(g_hout + ((size_t)rowA*TT + tA)*HH);
  const float4* pb = (const float4*)(g_hout + ((size_t)rowB*TT + tB)*HH);
  float4 a = pa[lane], b4 = pb[lane];
  float dx = a.x-b4.x, dy = a.y-b4.y, dz = a.z-b4.z, dw = a.w-b4.w;
  float s = dx*dx + dy*dy + dz*dz + dw*dw;
  #pragma unroll
  for (int off = 16; off; off >>= 1) s += __shfl_xor_sync(0xffffffffu, s, off);
  if (lane == 0) out[g] = __expf(-__fsqrt_rn(s));
}

extern "C" void kernel_launch(void* const* d_in, const int* in_sizes, int n_in,
                              void* d_out, int out_size)
{
  const float* traj = (const float*)d_in[0];
  const int*   Lt   = (const int*)  d_in[1];
  const int*   tasl = (const int*)  d_in[2];
  const int*   tfsl = (const int*)  d_in[3];
  const float* anch = (const float*)d_in[4];
  const int*   La   = (const int*)  d_in[5];
  const int*   asl  = (const int*)  d_in[6];
  const float* fare = (const float*)d_in[7];
  const int*   Lf   = (const int*)  d_in[8];
  const int*   fsl  = (const int*)  d_in[9];
  const float* W_ih = (const float*)d_in[10];
  const float* W_hh = (const float*)d_in[11];
  const float* b_ih = (const float*)d_in[12];
  const float* b_hh = (const float*)d_in[13];

  cudaFuncSetAttribute(lstm_kernel, cudaFuncAttributeMaxDynamicSharedMemorySize,
                       SM_BYTES);
  lstm_kernel<<<NBLOCKS, NTHREADS, SM_BYTES>>>(traj, anch, fare, W_ih, W_hh,
                                               b_ih, b_hh);
  dist_kernel<<<(4840*32 + 255)/256, 256>>>(Lt, La, Lf, tasl, tfsl, asl, fsl,
                                            (float*)d_out);
}